// round 1
// baseline (speedup 1.0000x reference)
#include <cuda_runtime.h>
#include <cuda_bf16.h>
#include <cstdint>

// Problem constants (MoELayer: B=2, T=2048, C=1024, E=8, H=4096, TOP_K=2)
#define NT   4096      // B*T tokens
#define CDIM 1024
#define HDIM 4096
#define NEXP 8

#define BM 128
#define BN 128
#define BK 16

// ---------------- scratch (device globals; no allocation allowed) ----------
__device__ int   g_counts[NEXP];
__device__ int   g_buckets[NEXP * NT];          // entries: token*2 + slot
__device__ float g_gatew[NT * 2];               // gate weight per (token, slot)
__device__ float g_h[(size_t)NEXP * NT * HDIM]; // per-expert hidden activations
__device__ float g_ypart[(size_t)NT * 2 * CDIM];// per (token,slot) FFN output

// ---------------- init --------------------------------------------------
__global__ void init_kernel() {
    int i = threadIdx.x;
    if (i < NEXP) g_counts[i] = 0;
}

// ---------------- router: logits, softmax, top-2, bucket append ----------
__global__ void router_kernel(const float* __restrict__ x,
                              const float* __restrict__ rw) {
    int warp = (blockIdx.x * blockDim.x + threadIdx.x) >> 5;
    int lane = threadIdx.x & 31;
    if (warp >= NT) return;
    const float* xt = x + (size_t)warp * CDIM;

    float logits[NEXP];
    #pragma unroll
    for (int e = 0; e < NEXP; e++) {
        const float* w = rw + e * CDIM;
        float s = 0.f;
        for (int k = lane; k < CDIM; k += 32) s += xt[k] * w[k];
        #pragma unroll
        for (int o = 16; o > 0; o >>= 1) s += __shfl_xor_sync(0xffffffffu, s, o);
        logits[e] = s;   // all lanes hold the full sum
    }
    float mx = logits[0];
    #pragma unroll
    for (int e = 1; e < NEXP; e++) mx = fmaxf(mx, logits[e]);
    float p[NEXP], sum = 0.f;
    #pragma unroll
    for (int e = 0; e < NEXP; e++) { p[e] = expf(logits[e] - mx); sum += p[e]; }
    #pragma unroll
    for (int e = 0; e < NEXP; e++) p[e] /= sum;

    // top-2 (ties -> lowest index, matching jax.lax.top_k)
    int i0 = 0;
    #pragma unroll
    for (int e = 1; e < NEXP; e++) if (p[e] > p[i0]) i0 = e;
    int i1 = -1;
    #pragma unroll
    for (int e = 0; e < NEXP; e++) {
        if (e == i0) continue;
        if (i1 < 0 || p[e] > p[i1]) i1 = e;
    }
    float w0 = p[i0], w1 = p[i1], t = w0 + w1;
    w0 /= t; w1 /= t;

    if (lane == 0) {
        g_gatew[warp * 2 + 0] = w0;
        g_gatew[warp * 2 + 1] = w1;
        int p0 = atomicAdd(&g_counts[i0], 1);
        g_buckets[i0 * NT + p0] = warp * 2 + 0;
        int p1 = atomicAdd(&g_counts[i1], 1);
        g_buckets[i1 * NT + p1] = warp * 2 + 1;
    }
}

// ---------------- GEMM1: h = gelu(Xg @ w_fc[e] + b_fc[e]) ---------------
__device__ __forceinline__ float gelu_new(float v) {
    float u = v + 0.044715f * v * v * v;
    return 0.5f * v * (1.f + tanhf(0.7978845608028654f * u));
}

__global__ __launch_bounds__(256)
void gemm1_kernel(const float* __restrict__ x,
                  const float* __restrict__ w_fc,
                  const float* __restrict__ b_fc) {
    int e = blockIdx.z;
    int cnt = g_counts[e];
    int m0 = blockIdx.y * BM;
    if (m0 >= cnt) return;
    int n0 = blockIdx.x * BN;
    const float* B = w_fc + (size_t)e * CDIM * HDIM; // [C,H] row-major

    __shared__ float As[BK][BM + 1];
    __shared__ float Bs[BK][BN];
    __shared__ int   rowtok[BM];

    int tid = threadIdx.x;
    if (tid < BM) {
        int m = m0 + tid;
        rowtok[tid] = (m < cnt) ? (g_buckets[e * NT + m] >> 1) : -1;
    }
    __syncthreads();

    float acc[8][8] = {};
    int tx = tid & 15, ty = tid >> 4;

    for (int k0 = 0; k0 < CDIM; k0 += BK) {
        #pragma unroll
        for (int i = 0; i < 2; i++) {              // A tile: 128x16
            int idx = tid + i * 256;
            int r  = idx >> 2;
            int kq = (idx & 3) << 2;
            int tok = rowtok[r];
            float4 v = make_float4(0.f, 0.f, 0.f, 0.f);
            if (tok >= 0) v = *(const float4*)&x[(size_t)tok * CDIM + k0 + kq];
            As[kq + 0][r] = v.x; As[kq + 1][r] = v.y;
            As[kq + 2][r] = v.z; As[kq + 3][r] = v.w;
        }
        #pragma unroll
        for (int i = 0; i < 2; i++) {              // B tile: 16x128
            int idx = tid + i * 256;
            int r  = idx >> 5;
            int nq = (idx & 31) << 2;
            *(float4*)&Bs[r][nq] =
                *(const float4*)&B[(size_t)(k0 + r) * HDIM + n0 + nq];
        }
        __syncthreads();
        #pragma unroll
        for (int kk = 0; kk < BK; kk++) {
            float a[8], b[8];
            #pragma unroll
            for (int i = 0; i < 8; i++) a[i] = As[kk][ty * 8 + i];
            #pragma unroll
            for (int j = 0; j < 8; j++) b[j] = Bs[kk][tx * 8 + j];
            #pragma unroll
            for (int i = 0; i < 8; i++)
                #pragma unroll
                for (int j = 0; j < 8; j++)
                    acc[i][j] += a[i] * b[j];
        }
        __syncthreads();
    }

    #pragma unroll
    for (int i = 0; i < 8; i++) {
        int m = m0 + ty * 8 + i;
        if (m >= cnt) continue;
        float* hrow = g_h + ((size_t)e * NT + m) * HDIM + n0;
        #pragma unroll
        for (int j = 0; j < 8; j++) {
            int n = tx * 8 + j;
            float v = acc[i][j] + b_fc[e * HDIM + n0 + n];
            hrow[n] = gelu_new(v);
        }
    }
}

// ---------------- GEMM2: ypart = gate * (h @ w_proj[e] + b_proj[e]) -----
__global__ __launch_bounds__(256)
void gemm2_kernel(const float* __restrict__ w_proj,
                  const float* __restrict__ b_proj) {
    int e = blockIdx.z;
    int cnt = g_counts[e];
    int m0 = blockIdx.y * BM;
    if (m0 >= cnt) return;
    int n0 = blockIdx.x * BN;
    const float* B = w_proj + (size_t)e * HDIM * CDIM; // [H,C] row-major
    const float* A = g_h + (size_t)e * NT * HDIM;

    __shared__ float As[BK][BM + 1];
    __shared__ float Bs[BK][BN];

    int tid = threadIdx.x;
    float acc[8][8] = {};
    int tx = tid & 15, ty = tid >> 4;

    for (int k0 = 0; k0 < HDIM; k0 += BK) {
        #pragma unroll
        for (int i = 0; i < 2; i++) {              // A tile: 128x16
            int idx = tid + i * 256;
            int r  = idx >> 2;
            int kq = (idx & 3) << 2;
            int m = m0 + r;
            float4 v = make_float4(0.f, 0.f, 0.f, 0.f);
            if (m < cnt) v = *(const float4*)&A[(size_t)m * HDIM + k0 + kq];
            As[kq + 0][r] = v.x; As[kq + 1][r] = v.y;
            As[kq + 2][r] = v.z; As[kq + 3][r] = v.w;
        }
        #pragma unroll
        for (int i = 0; i < 2; i++) {              // B tile: 16x128
            int idx = tid + i * 256;
            int r  = idx >> 5;
            int nq = (idx & 31) << 2;
            *(float4*)&Bs[r][nq] =
                *(const float4*)&B[(size_t)(k0 + r) * CDIM + n0 + nq];
        }
        __syncthreads();
        #pragma unroll
        for (int kk = 0; kk < BK; kk++) {
            float a[8], b[8];
            #pragma unroll
            for (int i = 0; i < 8; i++) a[i] = As[kk][ty * 8 + i];
            #pragma unroll
            for (int j = 0; j < 8; j++) b[j] = Bs[kk][tx * 8 + j];
            #pragma unroll
            for (int i = 0; i < 8; i++)
                #pragma unroll
                for (int j = 0; j < 8; j++)
                    acc[i][j] += a[i] * b[j];
        }
        __syncthreads();
    }

    #pragma unroll
    for (int i = 0; i < 8; i++) {
        int m = m0 + ty * 8 + i;
        if (m >= cnt) continue;
        int entry = g_buckets[e * NT + m];        // token*2 + slot
        float g = g_gatew[entry];
        float* yrow = g_ypart + (size_t)entry * CDIM + n0;
        #pragma unroll
        for (int j = 0; j < 8; j++) {
            int n = tx * 8 + j;
            yrow[n] = g * (acc[i][j] + b_proj[e * CDIM + n0 + n]);
        }
    }
}

// ---------------- combine: out[t] = ypart[t,0] + ypart[t,1] -------------
__global__ void combine_kernel(float* __restrict__ out) {
    int idx = blockIdx.x * blockDim.x + threadIdx.x; // over NT*CDIM/4
    const int C4 = CDIM / 4;
    if (idx >= NT * C4) return;
    int tok = idx / C4;
    int c4  = idx - tok * C4;
    const float4* yp = (const float4*)g_ypart;
    float4 a = yp[(size_t)(tok * 2 + 0) * C4 + c4];
    float4 b = yp[(size_t)(tok * 2 + 1) * C4 + c4];
    float4 r = make_float4(a.x + b.x, a.y + b.y, a.z + b.z, a.w + b.w);
    ((float4*)out)[idx] = r;
}

// ---------------- launch --------------------------------------------------
extern "C" void kernel_launch(void* const* d_in, const int* in_sizes, int n_in,
                              void* d_out, int out_size) {
    const float* x      = (const float*)d_in[0];
    const float* rw     = (const float*)d_in[1];
    const float* w_fc   = (const float*)d_in[2];
    const float* b_fc   = (const float*)d_in[3];
    const float* w_proj = (const float*)d_in[4];
    const float* b_proj = (const float*)d_in[5];
    float* out = (float*)d_out;

    init_kernel<<<1, 32>>>();
    router_kernel<<<(NT * 32 + 255) / 256, 256>>>(x, rw);
    gemm1_kernel<<<dim3(HDIM / BN, NT / BM, NEXP), 256>>>(x, w_fc, b_fc);
    gemm2_kernel<<<dim3(CDIM / BN, NT / BM, NEXP), 256>>>(w_proj, b_proj);
    combine_kernel<<<(NT * (CDIM / 4) + 255) / 256, 256>>>(out);
}

// round 5
// speedup vs baseline: 2.2165x; 2.2165x over previous
#include <cuda_runtime.h>
#include <cuda_bf16.h>
#include <cstdint>

// MoELayer: B=2, T=2048, C=1024, E=8, H=4096, TOP_K=2
#define NT   4096
#define CDIM 1024
#define HDIM 4096
#define NEXP 8

#define BM 128
#define BN 128
#define KC 64                 // k-elements per chunk
#define ROWE 72               // padded row stride in bf16 elements (64 + 8)
#define TILE_E (128 * ROWE)   // elements per tile
#define SMEM_DYN (4 * TILE_E * 2)   // AH, AL, BH, BL  (73728 B)

// ---------------- scratch (device globals) --------------------------------
__device__ int   g_counts[NEXP];
__device__ int   g_buckets[NEXP * NT];            // entry = token*2 + slot
__device__ float g_gatew[NT * 2];
__device__ __nv_bfloat16 g_x_hi[NT * CDIM];
__device__ __nv_bfloat16 g_x_lo[NT * CDIM];
__device__ __nv_bfloat16 g_wfcT_hi[(size_t)NEXP * HDIM * CDIM]; // [E][H][C]
__device__ __nv_bfloat16 g_wfcT_lo[(size_t)NEXP * HDIM * CDIM];
__device__ __nv_bfloat16 g_wprT_hi[(size_t)NEXP * CDIM * HDIM]; // [E][C][H]
__device__ __nv_bfloat16 g_wprT_lo[(size_t)NEXP * CDIM * HDIM];
__device__ __nv_bfloat16 g_h_hi[(size_t)2 * NT * HDIM];         // [entry][H]
__device__ __nv_bfloat16 g_h_lo[(size_t)2 * NT * HDIM];
__device__ float g_ypart[(size_t)2 * NT * CDIM];                // [entry][C]

// ---------------- mma -----------------------------------------------------
__device__ __forceinline__ void mma_bf16(float* c, const uint32_t* a,
                                         const uint32_t* b) {
    asm volatile(
        "mma.sync.aligned.m16n8k16.row.col.f32.bf16.bf16.f32 "
        "{%0,%1,%2,%3},{%4,%5,%6,%7},{%8,%9},{%0,%1,%2,%3};"
        : "+f"(c[0]), "+f"(c[1]), "+f"(c[2]), "+f"(c[3])
        : "r"(a[0]), "r"(a[1]), "r"(a[2]), "r"(a[3]), "r"(b[0]), "r"(b[1]));
}

// ---------------- init / router -------------------------------------------
__global__ void init_kernel() { if (threadIdx.x < NEXP) g_counts[threadIdx.x] = 0; }

__global__ void router_kernel(const float* __restrict__ x,
                              const float* __restrict__ rw) {
    int warp = (blockIdx.x * blockDim.x + threadIdx.x) >> 5;
    int lane = threadIdx.x & 31;
    if (warp >= NT) return;
    const float* xt = x + (size_t)warp * CDIM;
    float logits[NEXP];
    #pragma unroll
    for (int e = 0; e < NEXP; e++) {
        const float* w = rw + e * CDIM;
        float s = 0.f;
        for (int k = lane; k < CDIM; k += 32) s += xt[k] * w[k];
        #pragma unroll
        for (int o = 16; o > 0; o >>= 1) s += __shfl_xor_sync(0xffffffffu, s, o);
        logits[e] = s;
    }
    float mx = logits[0];
    #pragma unroll
    for (int e = 1; e < NEXP; e++) mx = fmaxf(mx, logits[e]);
    float p[NEXP], sum = 0.f;
    #pragma unroll
    for (int e = 0; e < NEXP; e++) { p[e] = expf(logits[e] - mx); sum += p[e]; }
    #pragma unroll
    for (int e = 0; e < NEXP; e++) p[e] /= sum;
    int i0 = 0;
    #pragma unroll
    for (int e = 1; e < NEXP; e++) if (p[e] > p[i0]) i0 = e;
    int i1 = -1;
    #pragma unroll
    for (int e = 0; e < NEXP; e++) {
        if (e == i0) continue;
        if (i1 < 0 || p[e] > p[i1]) i1 = e;
    }
    float w0 = p[i0], w1 = p[i1], t = w0 + w1;
    if (lane == 0) {
        g_gatew[warp * 2 + 0] = w0 / t;
        g_gatew[warp * 2 + 1] = w1 / t;
        int p0 = atomicAdd(&g_counts[i0], 1);
        g_buckets[i0 * NT + p0] = warp * 2 + 0;
        int p1 = atomicAdd(&g_counts[i1], 1);
        g_buckets[i1 * NT + p1] = warp * 2 + 1;
    }
}

// ---------------- prep ----------------------------------------------------
__global__ void convert_x_kernel(const float* __restrict__ x) {
    int i = blockIdx.x * blockDim.x + threadIdx.x;
    if (i >= NT * CDIM) return;
    float f = x[i];
    __nv_bfloat16 hi = __float2bfloat16(f);
    g_x_hi[i] = hi;
    g_x_lo[i] = __float2bfloat16(f - __bfloat162float(hi));
}

// W=0: w_fc [E][CDIM][HDIM] -> g_wfcT [E][HDIM][CDIM]
// W=1: w_proj [E][HDIM][CDIM] -> g_wprT [E][CDIM][HDIM]
// NOTE: destination pointers resolved IN DEVICE CODE (host-side &__device__
// symbol is the host shadow address — GB300 ATS makes that a silent write
// to host memory, which was the R3/R4 zero-weight bug).
template <int W>
__global__ void split_transpose_kernel(const float* __restrict__ src) {
    const int R  = W ? HDIM : CDIM;   // src rows
    const int Cc = W ? CDIM : HDIM;   // src cols
    __nv_bfloat16* dh = W ? g_wprT_hi : g_wfcT_hi;
    __nv_bfloat16* dl = W ? g_wprT_lo : g_wfcT_lo;
    __shared__ float t[32][33];
    size_t eoff = (size_t)blockIdx.z * R * Cc;
    int c0 = blockIdx.x * 32, r0 = blockIdx.y * 32;
    int tx = threadIdx.x, ty = threadIdx.y;
    #pragma unroll
    for (int i = ty; i < 32; i += 8)
        t[i][tx] = src[eoff + (size_t)(r0 + i) * Cc + c0 + tx];
    __syncthreads();
    #pragma unroll
    for (int i = ty; i < 32; i += 8) {
        float f = t[tx][i];
        __nv_bfloat16 hi = __float2bfloat16(f);
        size_t o = eoff + (size_t)(c0 + i) * R + r0 + tx;
        dh[o] = hi;
        dl[o] = __float2bfloat16(f - __bfloat162float(hi));
    }
}

__device__ __forceinline__ float gelu_new(float v) {
    float u = v + 0.044715f * v * v * v;
    return 0.5f * v * (1.f + tanhf(0.7978845608028654f * u));
}

// ---------------- chunk loader (plain LDG->STS) ---------------------------
// smem layout: 4 tiles [AH][AL][BH][BL], each [128][ROWE] bf16
__device__ __forceinline__ void load_chunk(
    __nv_bfloat16* sm, const __nv_bfloat16* __restrict__ Ah,
    const __nv_bfloat16* __restrict__ Al, int strideA, int eshift,
    const int* __restrict__ entryArr, const __nv_bfloat16* __restrict__ Bh,
    const __nv_bfloat16* __restrict__ Bl, int strideB, int n0, int k0,
    int tid) {
    #pragma unroll
    for (int t = 0; t < 16; t++) {
        int idx = tid + t * 256;
        int r = (idx >> 3) & 127;
        int c8 = idx & 7;
        const int tile = t >> 2;                // 0=AH 1=AL 2=BH 3=BL
        uint4 v = make_uint4(0, 0, 0, 0);
        if (tile < 2) {
            const __nv_bfloat16* base = (tile == 0) ? Ah : Al;
            int en = entryArr[r];
            if (en >= 0)
                v = *(const uint4*)(base + (size_t)(en >> eshift) * strideA +
                                    k0 + c8 * 8);
        } else {
            const __nv_bfloat16* base = (tile == 2) ? Bh : Bl;
            v = *(const uint4*)(base + (size_t)(n0 + r) * strideB + k0 + c8 * 8);
        }
        *(uint4*)(sm + tile * TILE_E + r * ROWE + c8 * 8) = v;
    }
}

// ---------------- fused GEMM (mma.sync bf16 split, direct LDS frags) ------
// P2 = 0: h = gelu(Xg @ wfcT^T + b_fc)  -> g_h hi/lo
// P2 = 1: ypart = gate * (h @ wprT^T + b_proj)
template <int P2>
__global__ __launch_bounds__(256, 2) void gemm_mma(const float* __restrict__ bias) {
    const int NDIM = P2 ? CDIM : HDIM;
    const int KD   = P2 ? HDIM : CDIM;
    const int NCH  = KD / KC;

    int e = blockIdx.z;
    int cnt = g_counts[e];
    int m0 = blockIdx.y * BM;
    if (m0 >= cnt) return;
    int n0 = blockIdx.x * BN;

    const __nv_bfloat16* Ah = P2 ? g_h_hi : g_x_hi;
    const __nv_bfloat16* Al = P2 ? g_h_lo : g_x_lo;
    const int eshift = P2 ? 0 : 1;
    const __nv_bfloat16* Bh =
        P2 ? (g_wprT_hi + (size_t)e * CDIM * HDIM)
           : (g_wfcT_hi + (size_t)e * HDIM * CDIM);
    const __nv_bfloat16* Bl =
        P2 ? (g_wprT_lo + (size_t)e * CDIM * HDIM)
           : (g_wfcT_lo + (size_t)e * HDIM * CDIM);

    extern __shared__ __nv_bfloat16 sm[];
    __shared__ int entryArr[BM];
    __nv_bfloat16* sAH = sm;
    __nv_bfloat16* sAL = sm + TILE_E;
    __nv_bfloat16* sBH = sm + 2 * TILE_E;
    __nv_bfloat16* sBL = sm + 3 * TILE_E;

    int tid = threadIdx.x;
    int wid = tid >> 5, lane = tid & 31;
    int wm = (wid >> 2) * 64, wn = (wid & 3) * 32;
    int gr = lane >> 2, gc2 = (lane & 3) * 2;

    if (tid < BM) {
        int m = m0 + tid;
        entryArr[tid] = (m < cnt) ? g_buckets[e * NT + m] : -1;
    }

    float acc[4][4][4] = {};

    for (int c = 0; c < NCH; c++) {
        __syncthreads();
        load_chunk(sm, Ah, Al, KD, eshift, entryArr, Bh, Bl, KD, n0, c * KC, tid);
        __syncthreads();
        #pragma unroll
        for (int s = 0; s < 4; s++) {
            int kof = s * 16;
            uint32_t bhf[4][2], blf[4][2];
            #pragma unroll
            for (int j = 0; j < 4; j++) {
                int nof = (wn + j * 8 + gr) * ROWE + kof + gc2;
                bhf[j][0] = *(const uint32_t*)(sBH + nof);
                bhf[j][1] = *(const uint32_t*)(sBH + nof + 8);
                blf[j][0] = *(const uint32_t*)(sBL + nof);
                blf[j][1] = *(const uint32_t*)(sBL + nof + 8);
            }
            #pragma unroll
            for (int i = 0; i < 4; i++) {
                int r0 = (wm + i * 16 + gr) * ROWE + kof + gc2;
                int r1 = r0 + 8 * ROWE;
                uint32_t ahf[4], alf[4];
                ahf[0] = *(const uint32_t*)(sAH + r0);
                ahf[1] = *(const uint32_t*)(sAH + r1);
                ahf[2] = *(const uint32_t*)(sAH + r0 + 8);
                ahf[3] = *(const uint32_t*)(sAH + r1 + 8);
                alf[0] = *(const uint32_t*)(sAL + r0);
                alf[1] = *(const uint32_t*)(sAL + r1);
                alf[2] = *(const uint32_t*)(sAL + r0 + 8);
                alf[3] = *(const uint32_t*)(sAL + r1 + 8);
                #pragma unroll
                for (int j = 0; j < 4; j++) {
                    mma_bf16(acc[i][j], ahf, bhf[j]);
                    mma_bf16(acc[i][j], ahf, blf[j]);
                    mma_bf16(acc[i][j], alf, bhf[j]);
                }
            }
        }
    }

    // epilogue: acc frag (row = wm+i*16+gr+h2*8, col = wn+j*8+gc2+{0,1})
    float bs[4][2];
    #pragma unroll
    for (int j = 0; j < 4; j++) {
        int n = n0 + wn + j * 8 + gc2;
        bs[j][0] = bias[e * NDIM + n];
        bs[j][1] = bias[e * NDIM + n + 1];
    }
    #pragma unroll
    for (int i = 0; i < 4; i++) {
        #pragma unroll
        for (int h2 = 0; h2 < 2; h2++) {
            int lr = wm + i * 16 + gr + h2 * 8;
            int entry = entryArr[lr];
            if (entry < 0) continue;
            if (P2 == 0) {
                uint32_t* dh = (uint32_t*)(g_h_hi + (size_t)entry * HDIM + n0 + wn);
                uint32_t* dl = (uint32_t*)(g_h_lo + (size_t)entry * HDIM + n0 + wn);
                #pragma unroll
                for (int j = 0; j < 4; j++) {
                    float v0 = acc[i][j][h2 * 2 + 0] + bs[j][0];
                    float v1 = acc[i][j][h2 * 2 + 1] + bs[j][1];
                    float q0 = gelu_new(v0), q1 = gelu_new(v1);
                    __nv_bfloat16 h0 = __float2bfloat16(q0);
                    __nv_bfloat16 h1 = __float2bfloat16(q1);
                    __nv_bfloat16 l0 = __float2bfloat16(q0 - __bfloat162float(h0));
                    __nv_bfloat16 l1 = __float2bfloat16(q1 - __bfloat162float(h1));
                    int w = (j * 8 + gc2) >> 1;
                    dh[w] = ((uint32_t)__bfloat16_as_ushort(h1) << 16) |
                            __bfloat16_as_ushort(h0);
                    dl[w] = ((uint32_t)__bfloat16_as_ushort(l1) << 16) |
                            __bfloat16_as_ushort(l0);
                }
            } else {
                float ga = g_gatew[entry];
                float2* dy = (float2*)(g_ypart + (size_t)entry * CDIM + n0 + wn);
                #pragma unroll
                for (int j = 0; j < 4; j++) {
                    float y0 = ga * (acc[i][j][h2 * 2 + 0] + bs[j][0]);
                    float y1 = ga * (acc[i][j][h2 * 2 + 1] + bs[j][1]);
                    dy[(j * 8 + gc2) >> 1] = make_float2(y0, y1);
                }
            }
        }
    }
}

// ---------------- combine -------------------------------------------------
__global__ void combine_kernel(float* __restrict__ out) {
    int idx = blockIdx.x * blockDim.x + threadIdx.x;
    const int C4 = CDIM / 4;
    if (idx >= NT * C4) return;
    int tok = idx / C4;
    int c4 = idx - tok * C4;
    const float4* yp = (const float4*)g_ypart;
    float4 a = yp[(size_t)(tok * 2 + 0) * C4 + c4];
    float4 b = yp[(size_t)(tok * 2 + 1) * C4 + c4];
    ((float4*)out)[idx] = make_float4(a.x + b.x, a.y + b.y, a.z + b.z, a.w + b.w);
}

// ---------------- launch --------------------------------------------------
extern "C" void kernel_launch(void* const* d_in, const int* in_sizes, int n_in,
                              void* d_out, int out_size) {
    const float* x      = (const float*)d_in[0];
    const float* rw     = (const float*)d_in[1];
    const float* w_fc   = (const float*)d_in[2];
    const float* b_fc   = (const float*)d_in[3];
    const float* w_proj = (const float*)d_in[4];
    const float* b_proj = (const float*)d_in[5];
    float* out = (float*)d_out;

    cudaFuncSetAttribute(gemm_mma<0>, cudaFuncAttributeMaxDynamicSharedMemorySize,
                         SMEM_DYN);
    cudaFuncSetAttribute(gemm_mma<1>, cudaFuncAttributeMaxDynamicSharedMemorySize,
                         SMEM_DYN);

    init_kernel<<<1, 32>>>();
    router_kernel<<<(NT * 32 + 255) / 256, 256>>>(x, rw);
    convert_x_kernel<<<(NT * CDIM + 255) / 256, 256>>>(x);
    // w_fc [E][C][H] -> g_wfcT [E][H][C]
    split_transpose_kernel<0><<<dim3(HDIM / 32, CDIM / 32, NEXP), dim3(32, 8)>>>(w_fc);
    // w_proj [E][H][C] -> g_wprT [E][C][H]
    split_transpose_kernel<1><<<dim3(CDIM / 32, HDIM / 32, NEXP), dim3(32, 8)>>>(w_proj);

    gemm_mma<0><<<dim3(HDIM / BN, NT / BM, NEXP), 256, SMEM_DYN>>>(b_fc);
    gemm_mma<1><<<dim3(CDIM / BN, NT / BM, NEXP), 256, SMEM_DYN>>>(b_proj);
    combine_kernel<<<(NT * (CDIM / 4) + 255) / 256, 256>>>(out);
}

// round 6
// speedup vs baseline: 2.4920x; 1.1243x over previous
#include <cuda_runtime.h>
#include <cuda_bf16.h>
#include <cstdint>

// MoELayer: B=2, T=2048, C=1024, E=8, H=4096, TOP_K=2
#define NT   4096
#define CDIM 1024
#define HDIM 4096
#define NEXP 8

#define BM 128
#define BN 128
#define KC 64                 // k-elements per chunk
#define ROWE 72               // padded row stride in bf16 elements (64 + 8)
#define TILE_E (128 * ROWE)   // elements per tile
#define STAGE_E (4 * TILE_E)  // AH, AL, BH, BL
#define SMEM_DYN (2 * STAGE_E * 2)   // 2 stages, bytes = 147456

// ---------------- scratch (device globals) --------------------------------
__device__ int   g_counts[NEXP];
__device__ int   g_buckets[NEXP * NT];            // entry = token*2 + slot
__device__ float g_gatew[NT * 2];
__device__ __nv_bfloat16 g_x_hi[NT * CDIM];
__device__ __nv_bfloat16 g_x_lo[NT * CDIM];
__device__ __nv_bfloat16 g_wfcT_hi[(size_t)NEXP * HDIM * CDIM]; // [E][H][C]
__device__ __nv_bfloat16 g_wfcT_lo[(size_t)NEXP * HDIM * CDIM];
__device__ __nv_bfloat16 g_wprT_hi[(size_t)NEXP * CDIM * HDIM]; // [E][C][H]
__device__ __nv_bfloat16 g_wprT_lo[(size_t)NEXP * CDIM * HDIM];
__device__ __nv_bfloat16 g_h_hi[(size_t)2 * NT * HDIM];         // [entry][H]
__device__ __nv_bfloat16 g_h_lo[(size_t)2 * NT * HDIM];
__device__ float g_ypart[(size_t)2 * NT * CDIM];                // [entry][C]

// ---------------- asm helpers ---------------------------------------------
__device__ __forceinline__ uint32_t smem_u32(const void* p) {
    uint32_t a;
    asm("{ .reg .u64 t; cvta.to.shared.u64 t, %1; cvt.u32.u64 %0, t; }"
        : "=r"(a) : "l"(p));
    return a;
}
__device__ __forceinline__ void cp16(uint32_t dst, const void* src, int sz) {
    asm volatile("cp.async.cg.shared.global [%0], [%1], 16, %2;"
                 :: "r"(dst), "l"(src), "r"(sz));
}
#define CP_COMMIT() asm volatile("cp.async.commit_group;" ::: "memory")
#define CP_WAIT(n)  asm volatile("cp.async.wait_group %0;" :: "n"(n) : "memory")
__device__ __forceinline__ void ldm_x4(uint32_t* r, uint32_t a) {
    asm volatile("ldmatrix.sync.aligned.m8n8.x4.shared.b16 {%0,%1,%2,%3}, [%4];"
                 : "=r"(r[0]), "=r"(r[1]), "=r"(r[2]), "=r"(r[3]) : "r"(a));
}
__device__ __forceinline__ void mma_bf16(float* c, const uint32_t* a,
                                         const uint32_t* b) {
    asm volatile(
        "mma.sync.aligned.m16n8k16.row.col.f32.bf16.bf16.f32 "
        "{%0,%1,%2,%3},{%4,%5,%6,%7},{%8,%9},{%0,%1,%2,%3};"
        : "+f"(c[0]), "+f"(c[1]), "+f"(c[2]), "+f"(c[3])
        : "r"(a[0]), "r"(a[1]), "r"(a[2]), "r"(a[3]), "r"(b[0]), "r"(b[1]));
}

// ---------------- init / router -------------------------------------------
__global__ void init_kernel() { if (threadIdx.x < NEXP) g_counts[threadIdx.x] = 0; }

__global__ void router_kernel(const float* __restrict__ x,
                              const float* __restrict__ rw) {
    int warp = (blockIdx.x * blockDim.x + threadIdx.x) >> 5;
    int lane = threadIdx.x & 31;
    if (warp >= NT) return;
    const float* xt = x + (size_t)warp * CDIM;
    float logits[NEXP];
    #pragma unroll
    for (int e = 0; e < NEXP; e++) {
        const float* w = rw + e * CDIM;
        float s = 0.f;
        for (int k = lane; k < CDIM; k += 32) s += xt[k] * w[k];
        #pragma unroll
        for (int o = 16; o > 0; o >>= 1) s += __shfl_xor_sync(0xffffffffu, s, o);
        logits[e] = s;
    }
    float mx = logits[0];
    #pragma unroll
    for (int e = 1; e < NEXP; e++) mx = fmaxf(mx, logits[e]);
    float p[NEXP], sum = 0.f;
    #pragma unroll
    for (int e = 0; e < NEXP; e++) { p[e] = expf(logits[e] - mx); sum += p[e]; }
    #pragma unroll
    for (int e = 0; e < NEXP; e++) p[e] /= sum;
    int i0 = 0;
    #pragma unroll
    for (int e = 1; e < NEXP; e++) if (p[e] > p[i0]) i0 = e;
    int i1 = -1;
    #pragma unroll
    for (int e = 0; e < NEXP; e++) {
        if (e == i0) continue;
        if (i1 < 0 || p[e] > p[i1]) i1 = e;
    }
    float w0 = p[i0], w1 = p[i1], t = w0 + w1;
    if (lane == 0) {
        g_gatew[warp * 2 + 0] = w0 / t;
        g_gatew[warp * 2 + 1] = w1 / t;
        int p0 = atomicAdd(&g_counts[i0], 1);
        g_buckets[i0 * NT + p0] = warp * 2 + 0;
        int p1 = atomicAdd(&g_counts[i1], 1);
        g_buckets[i1 * NT + p1] = warp * 2 + 1;
    }
}

// ---------------- prep ----------------------------------------------------
__global__ void convert_x_kernel(const float* __restrict__ x) {
    int i = blockIdx.x * blockDim.x + threadIdx.x;
    if (i >= NT * CDIM) return;
    float f = x[i];
    __nv_bfloat16 hi = __float2bfloat16(f);
    g_x_hi[i] = hi;
    g_x_lo[i] = __float2bfloat16(f - __bfloat162float(hi));
}

// W=0: w_fc [E][CDIM][HDIM] -> g_wfcT [E][HDIM][CDIM]
// W=1: w_proj [E][HDIM][CDIM] -> g_wprT [E][CDIM][HDIM]
// Destination pointers resolved IN DEVICE CODE (host-side &__device__ symbol
// is the host shadow address; GB300 ATS made that a silent host write).
template <int W>
__global__ void split_transpose_kernel(const float* __restrict__ src) {
    const int R  = W ? HDIM : CDIM;   // src rows
    const int Cc = W ? CDIM : HDIM;   // src cols
    __nv_bfloat16* dh = W ? g_wprT_hi : g_wfcT_hi;
    __nv_bfloat16* dl = W ? g_wprT_lo : g_wfcT_lo;
    __shared__ float t[32][33];
    size_t eoff = (size_t)blockIdx.z * R * Cc;
    int c0 = blockIdx.x * 32, r0 = blockIdx.y * 32;
    int tx = threadIdx.x & 31;
    int tid = threadIdx.x;
    // load 32x32 tile: t[i][tx] = src[r0+i][c0+tx]
    #pragma unroll
    for (int i = tid >> 5; i < 32; i += 8)
        t[i][tx] = src[eoff + (size_t)(r0 + i) * Cc + c0 + tx];
    __syncthreads();
    // write: out row (c0+cc), 4 consecutive r per thread, vectorized uint2
    int cc = tid >> 3;             // 0..31
    int rr = (tid & 7) * 4;        // 0..28
    __nv_bfloat16 hb[4], lb[4];
    #pragma unroll
    for (int q = 0; q < 4; q++) {
        float f = t[rr + q][cc];
        __nv_bfloat16 hi = __float2bfloat16(f);
        hb[q] = hi;
        lb[q] = __float2bfloat16(f - __bfloat162float(hi));
    }
    size_t o = eoff + (size_t)(c0 + cc) * R + r0 + rr;
    *(uint2*)(dh + o) = *(uint2*)hb;
    *(uint2*)(dl + o) = *(uint2*)lb;
}

__device__ __forceinline__ float gelu_new(float v) {
    float u = v + 0.044715f * v * v * v;
    return 0.5f * v * (1.f + tanhf(0.7978845608028654f * u));
}

// ---------------- async chunk loader --------------------------------------
// stage layout: 4 tiles [AH][AL][BH][BL], each [128][ROWE] bf16
__device__ __forceinline__ void load_chunk_async(
    uint32_t stage_u32, const __nv_bfloat16* __restrict__ Ah,
    const __nv_bfloat16* __restrict__ Al, int strideA, int eshift,
    const int* __restrict__ entryArr, const __nv_bfloat16* __restrict__ Bh,
    const __nv_bfloat16* __restrict__ Bl, int strideB, int n0, int k0,
    int tid) {
    #pragma unroll
    for (int t = 0; t < 16; t++) {
        int idx = tid + t * 256;
        int r = (idx >> 3) & 127;
        int c8 = idx & 7;
        const int tile = t >> 2;                // 0=AH 1=AL 2=BH 3=BL
        uint32_t dst = stage_u32 + (tile * TILE_E + r * ROWE + c8 * 8) * 2;
        if (tile < 2) {
            const __nv_bfloat16* base = (tile == 0) ? Ah : Al;
            int en = entryArr[r];
            if (en >= 0)
                cp16(dst, base + (size_t)(en >> eshift) * strideA + k0 + c8 * 8, 16);
            else
                cp16(dst, base, 0);             // zero-fill
        } else {
            const __nv_bfloat16* base = (tile == 2) ? Bh : Bl;
            cp16(dst, base + (size_t)(n0 + r) * strideB + k0 + c8 * 8, 16);
        }
    }
}

// ---------------- fused GEMM (mma.sync bf16 split, ldmatrix, cp.async) ----
// P2 = 0: h = gelu(Xg @ wfcT^T + b_fc)  -> g_h hi/lo
// P2 = 1: ypart = gate * (h @ wprT^T + b_proj)
template <int P2>
__global__ __launch_bounds__(256) void gemm_mma(const float* __restrict__ bias) {
    const int NDIM = P2 ? CDIM : HDIM;
    const int KD   = P2 ? HDIM : CDIM;
    const int NCH  = KD / KC;

    int e = blockIdx.z;
    int cnt = g_counts[e];
    int m0 = blockIdx.y * BM;
    if (m0 >= cnt) return;
    int n0 = blockIdx.x * BN;

    const __nv_bfloat16* Ah = P2 ? g_h_hi : g_x_hi;
    const __nv_bfloat16* Al = P2 ? g_h_lo : g_x_lo;
    const int eshift = P2 ? 0 : 1;
    const __nv_bfloat16* Bh =
        P2 ? (g_wprT_hi + (size_t)e * CDIM * HDIM)
           : (g_wfcT_hi + (size_t)e * HDIM * CDIM);
    const __nv_bfloat16* Bl =
        P2 ? (g_wprT_lo + (size_t)e * CDIM * HDIM)
           : (g_wfcT_lo + (size_t)e * HDIM * CDIM);

    extern __shared__ __nv_bfloat16 sm[];
    __shared__ int entryArr[BM];
    uint32_t sbase = smem_u32(sm);

    int tid = threadIdx.x;
    int wid = tid >> 5, lane = tid & 31;
    int wm = (wid >> 2) * 64, wn = (wid & 3) * 32;
    int gr = lane >> 2, gc2 = (lane & 3) * 2;

    // ldmatrix lane addressing (element offsets within a tile)
    int a_row = (lane & 15);                 // + wm + i*16
    int a_cof = (lane >> 4) * 8;             // + kof
    int bg = lane >> 3;
    int b_row = ((bg & 2) ? 8 : 0) + (lane & 7);   // + wn + j2*16
    int b_cof = (bg & 1) * 8;                // + kof

    if (tid < BM) {
        int m = m0 + tid;
        entryArr[tid] = (m < cnt) ? g_buckets[e * NT + m] : -1;
    }
    __syncthreads();

    // prologue: stage 0
    load_chunk_async(sbase, Ah, Al, KD, eshift, entryArr, Bh, Bl, KD, n0, 0, tid);
    CP_COMMIT();

    float acc[4][4][4] = {};

    for (int c = 0; c < NCH; c++) {
        if (c + 1 < NCH) {
            load_chunk_async(sbase + (uint32_t)(((c + 1) & 1) * STAGE_E * 2),
                             Ah, Al, KD, eshift, entryArr, Bh, Bl, KD, n0,
                             (c + 1) * KC, tid);
            CP_COMMIT();
            CP_WAIT(1);
        } else {
            CP_WAIT(0);
        }
        __syncthreads();

        uint32_t st = sbase + (uint32_t)((c & 1) * STAGE_E * 2);
        uint32_t stAH = st;
        uint32_t stAL = st + TILE_E * 2;
        uint32_t stBH = st + 2 * TILE_E * 2;
        uint32_t stBL = st + 3 * TILE_E * 2;

        #pragma unroll
        for (int s = 0; s < 4; s++) {
            int kof = s * 16;
            uint32_t bhf[4][2], blf[4][2];
            #pragma unroll
            for (int j2 = 0; j2 < 2; j2++) {
                uint32_t boff =
                    (uint32_t)(((wn + j2 * 16 + b_row) * ROWE + kof + b_cof) * 2);
                uint32_t r4[4];
                ldm_x4(r4, stBH + boff);
                bhf[j2 * 2][0] = r4[0]; bhf[j2 * 2][1] = r4[1];
                bhf[j2 * 2 + 1][0] = r4[2]; bhf[j2 * 2 + 1][1] = r4[3];
                ldm_x4(r4, stBL + boff);
                blf[j2 * 2][0] = r4[0]; blf[j2 * 2][1] = r4[1];
                blf[j2 * 2 + 1][0] = r4[2]; blf[j2 * 2 + 1][1] = r4[3];
            }
            #pragma unroll
            for (int i = 0; i < 4; i++) {
                uint32_t aoff =
                    (uint32_t)(((wm + i * 16 + a_row) * ROWE + kof + a_cof) * 2);
                uint32_t ahf[4], alf[4];
                ldm_x4(ahf, stAH + aoff);
                ldm_x4(alf, stAL + aoff);
                #pragma unroll
                for (int j = 0; j < 4; j++) {
                    mma_bf16(acc[i][j], ahf, bhf[j]);
                    mma_bf16(acc[i][j], ahf, blf[j]);
                    mma_bf16(acc[i][j], alf, bhf[j]);
                }
            }
        }
        __syncthreads();   // all warps done with stage (c&1) before next prefetch
    }

    // epilogue: acc frag (row = wm+i*16+gr+h2*8, col = wn+j*8+gc2+{0,1})
    float bs[4][2];
    #pragma unroll
    for (int j = 0; j < 4; j++) {
        int n = n0 + wn + j * 8 + gc2;
        bs[j][0] = bias[e * NDIM + n];
        bs[j][1] = bias[e * NDIM + n + 1];
    }
    #pragma unroll
    for (int i = 0; i < 4; i++) {
        #pragma unroll
        for (int h2 = 0; h2 < 2; h2++) {
            int lr = wm + i * 16 + gr + h2 * 8;
            int entry = entryArr[lr];
            if (entry < 0) continue;
            if (P2 == 0) {
                uint32_t* dh = (uint32_t*)(g_h_hi + (size_t)entry * HDIM + n0 + wn);
                uint32_t* dl = (uint32_t*)(g_h_lo + (size_t)entry * HDIM + n0 + wn);
                #pragma unroll
                for (int j = 0; j < 4; j++) {
                    float v0 = acc[i][j][h2 * 2 + 0] + bs[j][0];
                    float v1 = acc[i][j][h2 * 2 + 1] + bs[j][1];
                    float q0 = gelu_new(v0), q1 = gelu_new(v1);
                    __nv_bfloat16 h0 = __float2bfloat16(q0);
                    __nv_bfloat16 h1 = __float2bfloat16(q1);
                    __nv_bfloat16 l0 = __float2bfloat16(q0 - __bfloat162float(h0));
                    __nv_bfloat16 l1 = __float2bfloat16(q1 - __bfloat162float(h1));
                    int w = (j * 8 + gc2) >> 1;
                    dh[w] = ((uint32_t)__bfloat16_as_ushort(h1) << 16) |
                            __bfloat16_as_ushort(h0);
                    dl[w] = ((uint32_t)__bfloat16_as_ushort(l1) << 16) |
                            __bfloat16_as_ushort(l0);
                }
            } else {
                float ga = g_gatew[entry];
                float2* dy = (float2*)(g_ypart + (size_t)entry * CDIM + n0 + wn);
                #pragma unroll
                for (int j = 0; j < 4; j++) {
                    float y0 = ga * (acc[i][j][h2 * 2 + 0] + bs[j][0]);
                    float y1 = ga * (acc[i][j][h2 * 2 + 1] + bs[j][1]);
                    dy[(j * 8 + gc2) >> 1] = make_float2(y0, y1);
                }
            }
        }
    }
}

// ---------------- combine -------------------------------------------------
__global__ void combine_kernel(float* __restrict__ out) {
    int idx = blockIdx.x * blockDim.x + threadIdx.x;
    const int C4 = CDIM / 4;
    if (idx >= NT * C4) return;
    int tok = idx / C4;
    int c4 = idx - tok * C4;
    const float4* yp = (const float4*)g_ypart;
    float4 a = yp[(size_t)(tok * 2 + 0) * C4 + c4];
    float4 b = yp[(size_t)(tok * 2 + 1) * C4 + c4];
    ((float4*)out)[idx] = make_float4(a.x + b.x, a.y + b.y, a.z + b.z, a.w + b.w);
}

// ---------------- launch --------------------------------------------------
extern "C" void kernel_launch(void* const* d_in, const int* in_sizes, int n_in,
                              void* d_out, int out_size) {
    const float* x      = (const float*)d_in[0];
    const float* rw     = (const float*)d_in[1];
    const float* w_fc   = (const float*)d_in[2];
    const float* b_fc   = (const float*)d_in[3];
    const float* w_proj = (const float*)d_in[4];
    const float* b_proj = (const float*)d_in[5];
    float* out = (float*)d_out;

    cudaFuncSetAttribute(gemm_mma<0>, cudaFuncAttributeMaxDynamicSharedMemorySize,
                         SMEM_DYN);
    cudaFuncSetAttribute(gemm_mma<1>, cudaFuncAttributeMaxDynamicSharedMemorySize,
                         SMEM_DYN);

    init_kernel<<<1, 32>>>();
    router_kernel<<<(NT * 32 + 255) / 256, 256>>>(x, rw);
    convert_x_kernel<<<(NT * CDIM + 255) / 256, 256>>>(x);
    // w_fc [E][C][H] -> g_wfcT [E][H][C]
    split_transpose_kernel<0><<<dim3(HDIM / 32, CDIM / 32, NEXP), 256>>>(w_fc);
    // w_proj [E][H][C] -> g_wprT [E][C][H]
    split_transpose_kernel<1><<<dim3(CDIM / 32, HDIM / 32, NEXP), 256>>>(w_proj);

    gemm_mma<0><<<dim3(HDIM / BN, NT / BM, NEXP), 256, SMEM_DYN>>>(b_fc);
    gemm_mma<1><<<dim3(CDIM / BN, NT / BM, NEXP), 256, SMEM_DYN>>>(b_proj);
    combine_kernel<<<(NT * (CDIM / 4) + 255) / 256, 256>>>(out);
}

// round 7
// speedup vs baseline: 3.7642x; 1.5106x over previous
#include <cuda_runtime.h>
#include <cuda_fp16.h>
#include <cstdint>

// MoELayer: B=2, T=2048, C=1024, E=8, H=4096, TOP_K=2
#define NT   4096
#define CDIM 1024
#define HDIM 4096
#define NEXP 8

#define BM 128
#define BN 128
#define KC 64                 // k-elements per chunk
#define ROWE 72               // padded row stride in fp16 elements (64 + 8)
#define TILE_E (128 * ROWE)   // elements per tile
#define STAGE_E (3 * TILE_E)  // AH, BH, BL
#define SMEM_DYN (2 * STAGE_E * 2)   // 2 stages, bytes = 110592

// ---------------- scratch (device globals) --------------------------------
__device__ int   g_counts[NEXP];
__device__ int   g_buckets[NEXP * NT];            // entry = token*2 + slot
__device__ float g_gatew[NT * 2];
__device__ __half g_x_h[NT * CDIM];
__device__ __half g_wfcT_hi[(size_t)NEXP * HDIM * CDIM]; // [E][H][C]
__device__ __half g_wfcT_lo[(size_t)NEXP * HDIM * CDIM];
__device__ __half g_wprT_hi[(size_t)NEXP * CDIM * HDIM]; // [E][C][H]
__device__ __half g_wprT_lo[(size_t)NEXP * CDIM * HDIM];
__device__ __half g_h[(size_t)2 * NT * HDIM];            // [entry][H]
__device__ float g_ypart[(size_t)2 * NT * CDIM];         // [entry][C]

// ---------------- asm helpers ---------------------------------------------
__device__ __forceinline__ uint32_t smem_u32(const void* p) {
    uint32_t a;
    asm("{ .reg .u64 t; cvta.to.shared.u64 t, %1; cvt.u32.u64 %0, t; }"
        : "=r"(a) : "l"(p));
    return a;
}
__device__ __forceinline__ void cp16(uint32_t dst, const void* src, int sz) {
    asm volatile("cp.async.cg.shared.global [%0], [%1], 16, %2;"
                 :: "r"(dst), "l"(src), "r"(sz));
}
#define CP_COMMIT() asm volatile("cp.async.commit_group;" ::: "memory")
#define CP_WAIT(n)  asm volatile("cp.async.wait_group %0;" :: "n"(n) : "memory")
__device__ __forceinline__ void ldm_x4(uint32_t* r, uint32_t a) {
    asm volatile("ldmatrix.sync.aligned.m8n8.x4.shared.b16 {%0,%1,%2,%3}, [%4];"
                 : "=r"(r[0]), "=r"(r[1]), "=r"(r[2]), "=r"(r[3]) : "r"(a));
}
__device__ __forceinline__ void mma_fp16(float* c, const uint32_t* a,
                                         const uint32_t* b) {
    asm volatile(
        "mma.sync.aligned.m16n8k16.row.col.f32.f16.f16.f32 "
        "{%0,%1,%2,%3},{%4,%5,%6,%7},{%8,%9},{%0,%1,%2,%3};"
        : "+f"(c[0]), "+f"(c[1]), "+f"(c[2]), "+f"(c[3])
        : "r"(a[0]), "r"(a[1]), "r"(a[2]), "r"(a[3]), "r"(b[0]), "r"(b[1]));
}

// ---------------- init / router -------------------------------------------
__global__ void init_kernel() { if (threadIdx.x < NEXP) g_counts[threadIdx.x] = 0; }

__global__ void router_kernel(const float* __restrict__ x,
                              const float* __restrict__ rw) {
    int warp = (blockIdx.x * blockDim.x + threadIdx.x) >> 5;
    int lane = threadIdx.x & 31;
    if (warp >= NT) return;
    const float* xt = x + (size_t)warp * CDIM;
    float logits[NEXP];
    #pragma unroll
    for (int e = 0; e < NEXP; e++) {
        const float* w = rw + e * CDIM;
        float s = 0.f;
        for (int k = lane; k < CDIM; k += 32) s += xt[k] * w[k];
        #pragma unroll
        for (int o = 16; o > 0; o >>= 1) s += __shfl_xor_sync(0xffffffffu, s, o);
        logits[e] = s;
    }
    float mx = logits[0];
    #pragma unroll
    for (int e = 1; e < NEXP; e++) mx = fmaxf(mx, logits[e]);
    float p[NEXP], sum = 0.f;
    #pragma unroll
    for (int e = 0; e < NEXP; e++) { p[e] = expf(logits[e] - mx); sum += p[e]; }
    #pragma unroll
    for (int e = 0; e < NEXP; e++) p[e] /= sum;
    int i0 = 0;
    #pragma unroll
    for (int e = 1; e < NEXP; e++) if (p[e] > p[i0]) i0 = e;
    int i1 = -1;
    #pragma unroll
    for (int e = 0; e < NEXP; e++) {
        if (e == i0) continue;
        if (i1 < 0 || p[e] > p[i1]) i1 = e;
    }
    float w0 = p[i0], w1 = p[i1], t = w0 + w1;
    if (lane == 0) {
        g_gatew[warp * 2 + 0] = w0 / t;
        g_gatew[warp * 2 + 1] = w1 / t;
        int p0 = atomicAdd(&g_counts[i0], 1);
        g_buckets[i0 * NT + p0] = warp * 2 + 0;
        int p1 = atomicAdd(&g_counts[i1], 1);
        g_buckets[i1 * NT + p1] = warp * 2 + 1;
    }
}

// ---------------- prep ----------------------------------------------------
__global__ void convert_x_kernel(const float* __restrict__ x) {
    int i = blockIdx.x * blockDim.x + threadIdx.x;
    if (i >= NT * CDIM) return;
    g_x_h[i] = __float2half(x[i]);
}

// W=0: w_fc [E][CDIM][HDIM] -> g_wfcT [E][HDIM][CDIM] (fp16 hi/lo)
// W=1: w_proj [E][HDIM][CDIM] -> g_wprT [E][CDIM][HDIM]
// Destination pointers resolved IN DEVICE CODE (host-side &__device__ symbol
// is the host shadow address; GB300 ATS makes that a silent host write).
template <int W>
__global__ void split_transpose_kernel(const float* __restrict__ src) {
    const int R  = W ? HDIM : CDIM;   // src rows
    const int Cc = W ? CDIM : HDIM;   // src cols
    __half* dh = W ? g_wprT_hi : g_wfcT_hi;
    __half* dl = W ? g_wprT_lo : g_wfcT_lo;
    __shared__ float t[32][33];
    size_t eoff = (size_t)blockIdx.z * R * Cc;
    int c0 = blockIdx.x * 32, r0 = blockIdx.y * 32;
    int tx = threadIdx.x & 31;
    int tid = threadIdx.x;
    #pragma unroll
    for (int i = tid >> 5; i < 32; i += 8)
        t[i][tx] = src[eoff + (size_t)(r0 + i) * Cc + c0 + tx];
    __syncthreads();
    int cc = tid >> 3;             // 0..31
    int rr = (tid & 7) * 4;        // 0..28
    __half hb[4], lb[4];
    #pragma unroll
    for (int q = 0; q < 4; q++) {
        float f = t[rr + q][cc];
        __half hi = __float2half(f);
        hb[q] = hi;
        lb[q] = __float2half(f - __half2float(hi));
    }
    size_t o = eoff + (size_t)(c0 + cc) * R + r0 + rr;
    *(uint2*)(dh + o) = *(uint2*)hb;
    *(uint2*)(dl + o) = *(uint2*)lb;
}

__device__ __forceinline__ float gelu_new(float v) {
    float u = v + 0.044715f * v * v * v;
    return 0.5f * v * (1.f + tanhf(0.7978845608028654f * u));
}

// ---------------- async chunk loader --------------------------------------
// stage layout: 3 tiles [AH][BH][BL], each [128][ROWE] fp16
__device__ __forceinline__ void load_chunk_async(
    uint32_t stage_u32, const __half* __restrict__ Ah, int strideA, int eshift,
    const int* __restrict__ entryArr, const __half* __restrict__ Bh,
    const __half* __restrict__ Bl, int strideB, int n0, int k0, int tid) {
    #pragma unroll
    for (int t = 0; t < 12; t++) {
        int idx = tid + t * 256;
        int r = (idx >> 3) & 127;
        int c8 = idx & 7;
        const int tile = t >> 2;                // 0=AH 1=BH 2=BL
        uint32_t dst = stage_u32 + (tile * TILE_E + r * ROWE + c8 * 8) * 2;
        if (tile == 0) {
            int en = entryArr[r];
            if (en >= 0)
                cp16(dst, Ah + (size_t)(en >> eshift) * strideA + k0 + c8 * 8, 16);
            else
                cp16(dst, Ah, 0);               // zero-fill
        } else {
            const __half* base = (tile == 1) ? Bh : Bl;
            cp16(dst, base + (size_t)(n0 + r) * strideB + k0 + c8 * 8, 16);
        }
    }
}

// ---------------- fused GEMM (mma.sync fp16 2-term split) -----------------
// P2 = 0: h = gelu(Xg @ wfcT^T + b_fc)  -> g_h (fp16)
// P2 = 1: ypart = gate * (h @ wprT^T + b_proj)
template <int P2>
__global__ __launch_bounds__(256) void gemm_mma(const float* __restrict__ bias) {
    const int NDIM = P2 ? CDIM : HDIM;
    const int KD   = P2 ? HDIM : CDIM;
    const int NCH  = KD / KC;

    int e = blockIdx.z;
    int cnt = g_counts[e];
    int m0 = blockIdx.y * BM;
    if (m0 >= cnt) return;
    int n0 = blockIdx.x * BN;

    const __half* Ah = P2 ? g_h : g_x_h;
    const int eshift = P2 ? 0 : 1;
    const __half* Bh =
        P2 ? (g_wprT_hi + (size_t)e * CDIM * HDIM)
           : (g_wfcT_hi + (size_t)e * HDIM * CDIM);
    const __half* Bl =
        P2 ? (g_wprT_lo + (size_t)e * CDIM * HDIM)
           : (g_wfcT_lo + (size_t)e * HDIM * CDIM);

    extern __shared__ __half sm[];
    __shared__ int entryArr[BM];
    uint32_t sbase = smem_u32(sm);

    int tid = threadIdx.x;
    int wid = tid >> 5, lane = tid & 31;
    int wm = (wid >> 2) * 64, wn = (wid & 3) * 32;
    int gr = lane >> 2, gc2 = (lane & 3) * 2;

    // ldmatrix lane addressing (element offsets within a tile)
    int a_row = (lane & 15);
    int a_cof = (lane >> 4) * 8;
    int bg = lane >> 3;
    int b_row = ((bg & 2) ? 8 : 0) + (lane & 7);
    int b_cof = (bg & 1) * 8;

    if (tid < BM) {
        int m = m0 + tid;
        entryArr[tid] = (m < cnt) ? g_buckets[e * NT + m] : -1;
    }
    __syncthreads();

    load_chunk_async(sbase, Ah, KD, eshift, entryArr, Bh, Bl, KD, n0, 0, tid);
    CP_COMMIT();

    float acc[4][4][4] = {};

    for (int c = 0; c < NCH; c++) {
        if (c + 1 < NCH) {
            load_chunk_async(sbase + (uint32_t)(((c + 1) & 1) * STAGE_E * 2),
                             Ah, KD, eshift, entryArr, Bh, Bl, KD, n0,
                             (c + 1) * KC, tid);
            CP_COMMIT();
            CP_WAIT(1);
        } else {
            CP_WAIT(0);
        }
        __syncthreads();

        uint32_t st = sbase + (uint32_t)((c & 1) * STAGE_E * 2);
        uint32_t stAH = st;
        uint32_t stBH = st + TILE_E * 2;
        uint32_t stBL = st + 2 * TILE_E * 2;

        #pragma unroll
        for (int s = 0; s < 4; s++) {
            int kof = s * 16;
            uint32_t bhf[4][2], blf[4][2];
            #pragma unroll
            for (int j2 = 0; j2 < 2; j2++) {
                uint32_t boff =
                    (uint32_t)(((wn + j2 * 16 + b_row) * ROWE + kof + b_cof) * 2);
                uint32_t r4[4];
                ldm_x4(r4, stBH + boff);
                bhf[j2 * 2][0] = r4[0]; bhf[j2 * 2][1] = r4[1];
                bhf[j2 * 2 + 1][0] = r4[2]; bhf[j2 * 2 + 1][1] = r4[3];
                ldm_x4(r4, stBL + boff);
                blf[j2 * 2][0] = r4[0]; blf[j2 * 2][1] = r4[1];
                blf[j2 * 2 + 1][0] = r4[2]; blf[j2 * 2 + 1][1] = r4[3];
            }
            #pragma unroll
            for (int i = 0; i < 4; i++) {
                uint32_t aoff =
                    (uint32_t)(((wm + i * 16 + a_row) * ROWE + kof + a_cof) * 2);
                uint32_t ahf[4];
                ldm_x4(ahf, stAH + aoff);
                #pragma unroll
                for (int j = 0; j < 4; j++) {
                    mma_fp16(acc[i][j], ahf, bhf[j]);
                    mma_fp16(acc[i][j], ahf, blf[j]);
                }
            }
        }
        __syncthreads();
    }

    // epilogue: acc frag (row = wm+i*16+gr+h2*8, col = wn+j*8+gc2+{0,1})
    float bs[4][2];
    #pragma unroll
    for (int j = 0; j < 4; j++) {
        int n = n0 + wn + j * 8 + gc2;
        bs[j][0] = bias[e * NDIM + n];
        bs[j][1] = bias[e * NDIM + n + 1];
    }
    #pragma unroll
    for (int i = 0; i < 4; i++) {
        #pragma unroll
        for (int h2 = 0; h2 < 2; h2++) {
            int lr = wm + i * 16 + gr + h2 * 8;
            int entry = entryArr[lr];
            if (entry < 0) continue;
            if (P2 == 0) {
                uint32_t* dh = (uint32_t*)(g_h + (size_t)entry * HDIM + n0 + wn);
                #pragma unroll
                for (int j = 0; j < 4; j++) {
                    float v0 = acc[i][j][h2 * 2 + 0] + bs[j][0];
                    float v1 = acc[i][j][h2 * 2 + 1] + bs[j][1];
                    __half q0 = __float2half(gelu_new(v0));
                    __half q1 = __float2half(gelu_new(v1));
                    dh[(j * 8 + gc2) >> 1] =
                        ((uint32_t)__half_as_ushort(q1) << 16) |
                        __half_as_ushort(q0);
                }
            } else {
                float ga = g_gatew[entry];
                float2* dy = (float2*)(g_ypart + (size_t)entry * CDIM + n0 + wn);
                #pragma unroll
                for (int j = 0; j < 4; j++) {
                    float y0 = ga * (acc[i][j][h2 * 2 + 0] + bs[j][0]);
                    float y1 = ga * (acc[i][j][h2 * 2 + 1] + bs[j][1]);
                    dy[(j * 8 + gc2) >> 1] = make_float2(y0, y1);
                }
            }
        }
    }
}

// ---------------- combine -------------------------------------------------
__global__ void combine_kernel(float* __restrict__ out) {
    int idx = blockIdx.x * blockDim.x + threadIdx.x;
    const int C4 = CDIM / 4;
    if (idx >= NT * C4) return;
    int tok = idx / C4;
    int c4 = idx - tok * C4;
    const float4* yp = (const float4*)g_ypart;
    float4 a = yp[(size_t)(tok * 2 + 0) * C4 + c4];
    float4 b = yp[(size_t)(tok * 2 + 1) * C4 + c4];
    ((float4*)out)[idx] = make_float4(a.x + b.x, a.y + b.y, a.z + b.z, a.w + b.w);
}

// ---------------- launch --------------------------------------------------
extern "C" void kernel_launch(void* const* d_in, const int* in_sizes, int n_in,
                              void* d_out, int out_size) {
    const float* x      = (const float*)d_in[0];
    const float* rw     = (const float*)d_in[1];
    const float* w_fc   = (const float*)d_in[2];
    const float* b_fc   = (const float*)d_in[3];
    const float* w_proj = (const float*)d_in[4];
    const float* b_proj = (const float*)d_in[5];
    float* out = (float*)d_out;

    cudaFuncSetAttribute(gemm_mma<0>, cudaFuncAttributeMaxDynamicSharedMemorySize,
                         SMEM_DYN);
    cudaFuncSetAttribute(gemm_mma<1>, cudaFuncAttributeMaxDynamicSharedMemorySize,
                         SMEM_DYN);

    init_kernel<<<1, 32>>>();
    router_kernel<<<(NT * 32 + 255) / 256, 256>>>(x, rw);
    convert_x_kernel<<<(NT * CDIM + 255) / 256, 256>>>(x);
    // w_fc [E][C][H] -> g_wfcT [E][H][C]
    split_transpose_kernel<0><<<dim3(HDIM / 32, CDIM / 32, NEXP), 256>>>(w_fc);
    // w_proj [E][H][C] -> g_wprT [E][C][H]
    split_transpose_kernel<1><<<dim3(CDIM / 32, HDIM / 32, NEXP), 256>>>(w_proj);

    gemm_mma<0><<<dim3(HDIM / BN, NT / BM, NEXP), 256, SMEM_DYN>>>(b_fc);
    gemm_mma<1><<<dim3(CDIM / BN, NT / BM, NEXP), 256, SMEM_DYN>>>(b_proj);
    combine_kernel<<<(NT * (CDIM / 4) + 255) / 256, 256>>>(out);
}

// round 8
// speedup vs baseline: 6.4082x; 1.7024x over previous
#include <cuda_runtime.h>
#include <cuda_fp16.h>
#include <cstdint>

// MoELayer: B=2, T=2048, C=1024, E=8, H=4096, TOP_K=2
#define NT   4096
#define CDIM 1024
#define HDIM 4096
#define NEXP 8

#define BM 128
#define BN 128
#define KC 64                 // k-elements per chunk
#define ROWE 72               // padded row stride in fp16 elements (64 + 8)
#define TILE_E (128 * ROWE)   // elements per tile
#define STAGE_E (2 * TILE_E)  // A, B
#define SMEM_DYN (2 * STAGE_E * 2)   // 2 stages, bytes = 73728

// ---------------- scratch (device globals) --------------------------------
__device__ int   g_counts[NEXP];
__device__ int   g_buckets[NEXP * NT];            // entry = token*2 + slot
__device__ float g_gatew[NT * 2];
__device__ __half g_x_h[NT * CDIM];
__device__ __half g_wfcT[(size_t)NEXP * HDIM * CDIM];  // [E][H][C]
__device__ __half g_wprT[(size_t)NEXP * CDIM * HDIM];  // [E][C][H]
__device__ __half g_h[(size_t)2 * NT * HDIM];          // [entry][H]
__device__ float g_ypart[(size_t)2 * NT * CDIM];       // [entry][C]

// ---------------- asm helpers ---------------------------------------------
__device__ __forceinline__ uint32_t smem_u32(const void* p) {
    uint32_t a;
    asm("{ .reg .u64 t; cvta.to.shared.u64 t, %1; cvt.u32.u64 %0, t; }"
        : "=r"(a) : "l"(p));
    return a;
}
__device__ __forceinline__ void cp16(uint32_t dst, const void* src, int sz) {
    asm volatile("cp.async.cg.shared.global [%0], [%1], 16, %2;"
                 :: "r"(dst), "l"(src), "r"(sz));
}
#define CP_COMMIT() asm volatile("cp.async.commit_group;" ::: "memory")
#define CP_WAIT(n)  asm volatile("cp.async.wait_group %0;" :: "n"(n) : "memory")
__device__ __forceinline__ void ldm_x4(uint32_t* r, uint32_t a) {
    asm volatile("ldmatrix.sync.aligned.m8n8.x4.shared.b16 {%0,%1,%2,%3}, [%4];"
                 : "=r"(r[0]), "=r"(r[1]), "=r"(r[2]), "=r"(r[3]) : "r"(a));
}
__device__ __forceinline__ void mma_fp16(float* c, const uint32_t* a,
                                         const uint32_t* b) {
    asm volatile(
        "mma.sync.aligned.m16n8k16.row.col.f32.f16.f16.f32 "
        "{%0,%1,%2,%3},{%4,%5,%6,%7},{%8,%9},{%0,%1,%2,%3};"
        : "+f"(c[0]), "+f"(c[1]), "+f"(c[2]), "+f"(c[3])
        : "r"(a[0]), "r"(a[1]), "r"(a[2]), "r"(a[3]), "r"(b[0]), "r"(b[1]));
}

// ---------------- init / router -------------------------------------------
__global__ void init_kernel() { if (threadIdx.x < NEXP) g_counts[threadIdx.x] = 0; }

__global__ void router_kernel(const float* __restrict__ x,
                              const float* __restrict__ rw) {
    int warp = (blockIdx.x * blockDim.x + threadIdx.x) >> 5;
    int lane = threadIdx.x & 31;
    if (warp >= NT) return;
    const float* xt = x + (size_t)warp * CDIM;
    float logits[NEXP];
    #pragma unroll
    for (int e = 0; e < NEXP; e++) {
        const float* w = rw + e * CDIM;
        float s = 0.f;
        for (int k = lane; k < CDIM; k += 32) s += xt[k] * w[k];
        #pragma unroll
        for (int o = 16; o > 0; o >>= 1) s += __shfl_xor_sync(0xffffffffu, s, o);
        logits[e] = s;
    }
    float mx = logits[0];
    #pragma unroll
    for (int e = 1; e < NEXP; e++) mx = fmaxf(mx, logits[e]);
    float p[NEXP], sum = 0.f;
    #pragma unroll
    for (int e = 0; e < NEXP; e++) { p[e] = expf(logits[e] - mx); sum += p[e]; }
    #pragma unroll
    for (int e = 0; e < NEXP; e++) p[e] /= sum;
    int i0 = 0;
    #pragma unroll
    for (int e = 1; e < NEXP; e++) if (p[e] > p[i0]) i0 = e;
    int i1 = -1;
    #pragma unroll
    for (int e = 0; e < NEXP; e++) {
        if (e == i0) continue;
        if (i1 < 0 || p[e] > p[i1]) i1 = e;
    }
    float w0 = p[i0], w1 = p[i1], t = w0 + w1;
    if (lane == 0) {
        g_gatew[warp * 2 + 0] = w0 / t;
        g_gatew[warp * 2 + 1] = w1 / t;
        int p0 = atomicAdd(&g_counts[i0], 1);
        g_buckets[i0 * NT + p0] = warp * 2 + 0;
        int p1 = atomicAdd(&g_counts[i1], 1);
        g_buckets[i1 * NT + p1] = warp * 2 + 1;
    }
}

// ---------------- prep ----------------------------------------------------
__global__ void convert_x_kernel(const float* __restrict__ x) {
    int i = blockIdx.x * blockDim.x + threadIdx.x;
    if (i >= NT * CDIM) return;
    g_x_h[i] = __float2half(x[i]);
}

// W=0: w_fc [E][CDIM][HDIM] -> g_wfcT [E][HDIM][CDIM] (fp16)
// W=1: w_proj [E][HDIM][CDIM] -> g_wprT [E][CDIM][HDIM]
// 64-src-row tiles => 128B contiguous output stores per (block, out-row).
// Destination pointers resolved IN DEVICE CODE (host-side &__device__ symbol
// is the host shadow address; GB300 ATS makes that a silent host write).
template <int W>
__global__ void transpose_cvt_kernel(const float* __restrict__ src) {
    const int R  = W ? HDIM : CDIM;   // src rows
    const int Cc = W ? CDIM : HDIM;   // src cols
    __half* dst = W ? g_wprT : g_wfcT;
    __shared__ float t[64][33];
    size_t eoff = (size_t)blockIdx.z * R * Cc;
    int c0 = blockIdx.x * 32, r0 = blockIdx.y * 64;
    int tid = threadIdx.x;
    int tx = tid & 31;
    #pragma unroll
    for (int i = tid >> 5; i < 64; i += 8)
        t[i][tx] = src[eoff + (size_t)(r0 + i) * Cc + c0 + tx];
    __syncthreads();
    int cc = tid >> 3;             // 0..31  (output row = src col c0+cc)
    int rr = (tid & 7) * 8;        // 0..56
    __half hb[8];
    #pragma unroll
    for (int q = 0; q < 8; q++) hb[q] = __float2half(t[rr + q][cc]);
    size_t o = eoff + (size_t)(c0 + cc) * R + r0 + rr;
    *(uint4*)(dst + o) = *(uint4*)hb;
}

__device__ __forceinline__ float gelu_new(float v) {
    float u = v + 0.044715f * v * v * v;
    return 0.5f * v * (1.f + tanhf(0.7978845608028654f * u));
}

// ---------------- async chunk loader --------------------------------------
// stage layout: 2 tiles [A][B], each [128][ROWE] fp16
__device__ __forceinline__ void load_chunk_async(
    uint32_t stage_u32, const __half* __restrict__ A, int strideA, int eshift,
    const int* __restrict__ entryArr, const __half* __restrict__ B,
    int strideB, int n0, int k0, int tid) {
    #pragma unroll
    for (int t = 0; t < 8; t++) {
        int idx = tid + t * 256;
        int r = (idx >> 3) & 127;
        int c8 = idx & 7;
        const int tile = t >> 2;                // 0=A 1=B
        uint32_t dst = stage_u32 + (tile * TILE_E + r * ROWE + c8 * 8) * 2;
        if (tile == 0) {
            int en = entryArr[r];
            if (en >= 0)
                cp16(dst, A + (size_t)(en >> eshift) * strideA + k0 + c8 * 8, 16);
            else
                cp16(dst, A, 0);                // zero-fill
        } else {
            cp16(dst, B + (size_t)(n0 + r) * strideB + k0 + c8 * 8, 16);
        }
    }
}

// ---------------- fused GEMM (mma.sync fp16, single term) -----------------
// P2 = 0: h = gelu(Xg @ wfcT^T + b_fc)  -> g_h (fp16)
// P2 = 1: ypart = gate * (h @ wprT^T + b_proj)
template <int P2>
__global__ __launch_bounds__(256, 2) void gemm_mma(const float* __restrict__ bias) {
    const int NDIM = P2 ? CDIM : HDIM;
    const int KD   = P2 ? HDIM : CDIM;
    const int NCH  = KD / KC;

    int e = blockIdx.z;
    int cnt = g_counts[e];
    int m0 = blockIdx.y * BM;
    if (m0 >= cnt) return;
    int n0 = blockIdx.x * BN;

    const __half* A = P2 ? g_h : g_x_h;
    const int eshift = P2 ? 0 : 1;
    const __half* B = P2 ? (g_wprT + (size_t)e * CDIM * HDIM)
                         : (g_wfcT + (size_t)e * HDIM * CDIM);

    extern __shared__ __half sm[];
    __shared__ int entryArr[BM];
    uint32_t sbase = smem_u32(sm);

    int tid = threadIdx.x;
    int wid = tid >> 5, lane = tid & 31;
    int wm = (wid >> 2) * 64, wn = (wid & 3) * 32;
    int gr = lane >> 2, gc2 = (lane & 3) * 2;

    // ldmatrix lane addressing (element offsets within a tile)
    int a_row = (lane & 15);
    int a_cof = (lane >> 4) * 8;
    int bg = lane >> 3;
    int b_row = ((bg & 2) ? 8 : 0) + (lane & 7);
    int b_cof = (bg & 1) * 8;

    if (tid < BM) {
        int m = m0 + tid;
        entryArr[tid] = (m < cnt) ? g_buckets[e * NT + m] : -1;
    }
    __syncthreads();

    load_chunk_async(sbase, A, KD, eshift, entryArr, B, KD, n0, 0, tid);
    CP_COMMIT();

    float acc[4][4][4] = {};

    for (int c = 0; c < NCH; c++) {
        if (c + 1 < NCH) {
            load_chunk_async(sbase + (uint32_t)(((c + 1) & 1) * STAGE_E * 2),
                             A, KD, eshift, entryArr, B, KD, n0,
                             (c + 1) * KC, tid);
            CP_COMMIT();
            CP_WAIT(1);
        } else {
            CP_WAIT(0);
        }
        __syncthreads();

        uint32_t st = sbase + (uint32_t)((c & 1) * STAGE_E * 2);
        uint32_t stA = st;
        uint32_t stB = st + TILE_E * 2;

        #pragma unroll
        for (int s = 0; s < 4; s++) {
            int kof = s * 16;
            uint32_t bf[4][2];
            #pragma unroll
            for (int j2 = 0; j2 < 2; j2++) {
                uint32_t boff =
                    (uint32_t)(((wn + j2 * 16 + b_row) * ROWE + kof + b_cof) * 2);
                uint32_t r4[4];
                ldm_x4(r4, stB + boff);
                bf[j2 * 2][0] = r4[0]; bf[j2 * 2][1] = r4[1];
                bf[j2 * 2 + 1][0] = r4[2]; bf[j2 * 2 + 1][1] = r4[3];
            }
            #pragma unroll
            for (int i = 0; i < 4; i++) {
                uint32_t aoff =
                    (uint32_t)(((wm + i * 16 + a_row) * ROWE + kof + a_cof) * 2);
                uint32_t af[4];
                ldm_x4(af, stA + aoff);
                #pragma unroll
                for (int j = 0; j < 4; j++) mma_fp16(acc[i][j], af, bf[j]);
            }
        }
        __syncthreads();
    }

    // epilogue: acc frag (row = wm+i*16+gr+h2*8, col = wn+j*8+gc2+{0,1})
    float bs[4][2];
    #pragma unroll
    for (int j = 0; j < 4; j++) {
        int n = n0 + wn + j * 8 + gc2;
        bs[j][0] = bias[e * NDIM + n];
        bs[j][1] = bias[e * NDIM + n + 1];
    }
    #pragma unroll
    for (int i = 0; i < 4; i++) {
        #pragma unroll
        for (int h2 = 0; h2 < 2; h2++) {
            int lr = wm + i * 16 + gr + h2 * 8;
            int entry = entryArr[lr];
            if (entry < 0) continue;
            if (P2 == 0) {
                uint32_t* dh = (uint32_t*)(g_h + (size_t)entry * HDIM + n0 + wn);
                #pragma unroll
                for (int j = 0; j < 4; j++) {
                    float v0 = acc[i][j][h2 * 2 + 0] + bs[j][0];
                    float v1 = acc[i][j][h2 * 2 + 1] + bs[j][1];
                    __half q0 = __float2half(gelu_new(v0));
                    __half q1 = __float2half(gelu_new(v1));
                    dh[(j * 8 + gc2) >> 1] =
                        ((uint32_t)__half_as_ushort(q1) << 16) |
                        __half_as_ushort(q0);
                }
            } else {
                float ga = g_gatew[entry];
                float2* dy = (float2*)(g_ypart + (size_t)entry * CDIM + n0 + wn);
                #pragma unroll
                for (int j = 0; j < 4; j++) {
                    float y0 = ga * (acc[i][j][h2 * 2 + 0] + bs[j][0]);
                    float y1 = ga * (acc[i][j][h2 * 2 + 1] + bs[j][1]);
                    dy[(j * 8 + gc2) >> 1] = make_float2(y0, y1);
                }
            }
        }
    }
}

// ---------------- combine -------------------------------------------------
__global__ void combine_kernel(float* __restrict__ out) {
    int idx = blockIdx.x * blockDim.x + threadIdx.x;
    const int C4 = CDIM / 4;
    if (idx >= NT * C4) return;
    int tok = idx / C4;
    int c4 = idx - tok * C4;
    const float4* yp = (const float4*)g_ypart;
    float4 a = yp[(size_t)(tok * 2 + 0) * C4 + c4];
    float4 b = yp[(size_t)(tok * 2 + 1) * C4 + c4];
    ((float4*)out)[idx] = make_float4(a.x + b.x, a.y + b.y, a.z + b.z, a.w + b.w);
}

// ---------------- launch --------------------------------------------------
extern "C" void kernel_launch(void* const* d_in, const int* in_sizes, int n_in,
                              void* d_out, int out_size) {
    const float* x      = (const float*)d_in[0];
    const float* rw     = (const float*)d_in[1];
    const float* w_fc   = (const float*)d_in[2];
    const float* b_fc   = (const float*)d_in[3];
    const float* w_proj = (const float*)d_in[4];
    const float* b_proj = (const float*)d_in[5];
    float* out = (float*)d_out;

    cudaFuncSetAttribute(gemm_mma<0>, cudaFuncAttributeMaxDynamicSharedMemorySize,
                         SMEM_DYN);
    cudaFuncSetAttribute(gemm_mma<1>, cudaFuncAttributeMaxDynamicSharedMemorySize,
                         SMEM_DYN);

    init_kernel<<<1, 32>>>();
    router_kernel<<<(NT * 32 + 255) / 256, 256>>>(x, rw);
    convert_x_kernel<<<(NT * CDIM + 255) / 256, 256>>>(x);
    // w_fc [E][C][H] -> g_wfcT [E][H][C]
    transpose_cvt_kernel<0><<<dim3(HDIM / 32, CDIM / 64, NEXP), 256>>>(w_fc);
    // w_proj [E][H][C] -> g_wprT [E][C][H]
    transpose_cvt_kernel<1><<<dim3(CDIM / 32, HDIM / 64, NEXP), 256>>>(w_proj);

    gemm_mma<0><<<dim3(HDIM / BN, NT / BM, NEXP), 256, SMEM_DYN>>>(b_fc);
    gemm_mma<1><<<dim3(CDIM / BN, NT / BM, NEXP), 256, SMEM_DYN>>>(b_proj);
    combine_kernel<<<(NT * (CDIM / 4) + 255) / 256, 256>>>(out);
}